// round 16
// baseline (speedup 1.0000x reference)
#include <cuda_runtime.h>
#include <cuda_bf16.h>
#include <math.h>
#include <stdint.h>

#define T_DIM 64
#define B_DIM 512
#define D_DIM 768
#define H_DIM 12
#define HD_DIM 64
#define D3 (3 * D_DIM)
#define M_DIM (T_DIM * B_DIM)   // 32768

// ---------------------------------------------------------------------------
// Scratch (allocation-free rule: __device__ globals)
// ---------------------------------------------------------------------------
__device__ __nv_bfloat16 g_qkvh[(size_t)M_DIM * D3];
__device__ __nv_bfloat16 g_qkvl[(size_t)M_DIM * D3];
__device__ float g_out[(size_t)M_DIM * D_DIM];
__device__ __nv_bfloat16 g_nhi[(size_t)M_DIM * D_DIM];
__device__ __nv_bfloat16 g_nlo[(size_t)M_DIM * D_DIM];
__device__ __nv_bfloat16 g_chi[(size_t)M_DIM * D_DIM];
__device__ __nv_bfloat16 g_clo[(size_t)M_DIM * D_DIM];
__device__ __nv_bfloat16 g_wihi[(size_t)D3 * D_DIM];
__device__ __nv_bfloat16 g_wilo[(size_t)D3 * D_DIM];
__device__ __nv_bfloat16 g_wohi[(size_t)D_DIM * D_DIM];
__device__ __nv_bfloat16 g_wolo[(size_t)D_DIM * D_DIM];
__device__ float g_inv[M_DIM];
__device__ float g_mean[T_DIM * D_DIM];

// ---------------------------------------------------------------------------
// Portable PTX helpers
// ---------------------------------------------------------------------------
__device__ __forceinline__ void cpa16(uint32_t dst, const void* src) {
    asm volatile("cp.async.cg.shared.global [%0], [%1], 16;"
                 :: "r"(dst), "l"(src) : "memory");
}
__device__ __forceinline__ void cpa_commit() {
    asm volatile("cp.async.commit_group;" ::: "memory");
}
__device__ __forceinline__ void cpa_wait0() {
    asm volatile("cp.async.wait_group 0;" ::: "memory");
}

#define MMA16816(d, a, b)                                                   \
    asm volatile(                                                           \
        "mma.sync.aligned.m16n8k16.row.col.f32.bf16.bf16.f32 "             \
        "{%0,%1,%2,%3}, {%4,%5,%6,%7}, {%8,%9}, {%0,%1,%2,%3};"            \
        : "+f"((d)[0]), "+f"((d)[1]), "+f"((d)[2]), "+f"((d)[3])            \
        : "r"((a)[0]), "r"((a)[1]), "r"((a)[2]), "r"((a)[3]),               \
          "r"((b)[0]), "r"((b)[1]))

#define LDSM4(r, addr)                                                      \
    asm volatile("ldmatrix.sync.aligned.m8n8.x4.shared.b16 {%0,%1,%2,%3}, [%4];" \
        : "=r"((r)[0]), "=r"((r)[1]), "=r"((r)[2]), "=r"((r)[3]) : "r"(addr))

#define LDSM4T(r, addr)                                                     \
    asm volatile("ldmatrix.sync.aligned.m8n8.x4.trans.shared.b16 {%0,%1,%2,%3}, [%4];" \
        : "=r"((r)[0]), "=r"((r)[1]), "=r"((r)[2]), "=r"((r)[3]) : "r"(addr))

__device__ __forceinline__ void split2(float v, __nv_bfloat16& h, __nv_bfloat16& l) {
    h = __float2bfloat16(v);
    l = __float2bfloat16(v - __bfloat162float(h));
}
__device__ __forceinline__ uint32_t packbf(float a, float b) {
    __nv_bfloat162 t; t.x = __float2bfloat16(a); t.y = __float2bfloat16(b);
    return *(uint32_t*)&t;
}

// ---------------------------------------------------------------------------
// fp32 -> bf16 hi/lo split
// ---------------------------------------------------------------------------
__global__ __launch_bounds__(256) void split_kernel(
    const float* __restrict__ x, __nv_bfloat16* __restrict__ hi,
    __nv_bfloat16* __restrict__ lo, int n)
{
    int i = (blockIdx.x * 256 + threadIdx.x) * 4;
    if (i >= n) return;
    float4 v = *(const float4*)(x + i);
    __nv_bfloat16 h0, h1, h2, h3, l0, l1, l2, l3;
    split2(v.x, h0, l0); split2(v.y, h1, l1);
    split2(v.z, h2, l2); split2(v.w, h3, l3);
    __nv_bfloat162 hh0; hh0.x = h0; hh0.y = h1;
    __nv_bfloat162 hh1; hh1.x = h2; hh1.y = h3;
    __nv_bfloat162 ll0; ll0.x = l0; ll0.y = l1;
    __nv_bfloat162 ll1; ll1.x = l2; ll1.y = l3;
    *(__nv_bfloat162*)(hi + i)     = hh0;
    *(__nv_bfloat162*)(hi + i + 2) = hh1;
    *(__nv_bfloat162*)(lo + i)     = ll0;
    *(__nv_bfloat162*)(lo + i + 2) = ll1;
}

// ---------------------------------------------------------------------------
// mma.sync split-bf16 GEMM (NT). MMA issue is PASS-OUTERMOST: dependent
// MMAs on the same accumulator are 16 issues apart (was 1 -> HMMA-latency
// stall per MMA). Per-acc accumulation order unchanged (hh,lh,hl per ks)
// => bit-identical results.
// ---------------------------------------------------------------------------
#define SA 40
#define TILE_H (128 * SA)
#define GEMM_SMEM (2 * 4 * TILE_H * 2)

template <int SPLIT_OUT>
__global__ __launch_bounds__(256, 2) void gemm_mma(
    const __nv_bfloat16* __restrict__ Ahi, const __nv_bfloat16* __restrict__ Alo,
    const __nv_bfloat16* __restrict__ Bhi, const __nv_bfloat16* __restrict__ Blo,
    const float* __restrict__ bias, float* __restrict__ C,
    __nv_bfloat16* __restrict__ Chi, __nv_bfloat16* __restrict__ Clo,
    int N, int K)
{
    extern __shared__ __nv_bfloat16 sh[];
    const uint32_t sbase = (uint32_t)__cvta_generic_to_shared(sh);
    const int tid = threadIdx.x;
    const int wid = tid >> 5, lane = tid & 31;
    const int warp_m = wid >> 2, warp_n = wid & 3;
    const int bm = blockIdx.y * 128, bn = blockIdx.x * 128;

    const int lrow = tid >> 1;
    const int lofs = (tid & 1) * 16;
    const __nv_bfloat16* srcs[4];
    srcs[0] = Ahi + (size_t)(bm + lrow) * K + lofs;
    srcs[1] = Alo + (size_t)(bm + lrow) * K + lofs;
    srcs[2] = Bhi + (size_t)(bn + lrow) * K + lofs;
    srcs[3] = Blo + (size_t)(bn + lrow) * K + lofs;
    const uint32_t sdst = sbase + (uint32_t)(lrow * SA + lofs) * 2;

    const uint32_t a_loff =
        (uint32_t)(((warp_m * 64 + (lane & 15)) * SA + (lane >> 4) * 8) * 2);
    const uint32_t b_loff =
        (uint32_t)(((warp_n * 32 + (lane & 7) + ((lane >> 4) & 1) * 8) * SA +
                    ((lane >> 3) & 1) * 8) * 2);

    const int nchunks = K >> 5;

#pragma unroll
    for (int tI = 0; tI < 4; tI++) {
        uint32_t d = sdst + tI * TILE_H * 2;
        cpa16(d, srcs[tI]);
        cpa16(d + 16, srcs[tI] + 8);
    }
    cpa_commit();

    float acc[4][4][4];
#pragma unroll
    for (int mi = 0; mi < 4; mi++)
#pragma unroll
        for (int ni = 0; ni < 4; ni++)
#pragma unroll
            for (int j = 0; j < 4; j++) acc[mi][ni][j] = 0.f;

    for (int c = 0; c < nchunks; ++c) {
        cpa_wait0();
        __syncthreads();

        if (c + 1 < nchunks) {
            const int s1 = (c + 1) & 1;
            const int ko = (c + 1) * 32;
#pragma unroll
            for (int tI = 0; tI < 4; tI++) {
                uint32_t d = sdst + (s1 * 4 + tI) * TILE_H * 2;
                cpa16(d, srcs[tI] + ko);
                cpa16(d + 16, srcs[tI] + ko + 8);
            }
            cpa_commit();
        }

        const uint32_t st   = sbase + (uint32_t)((c & 1) * 4) * TILE_H * 2;
        const uint32_t uAhi = st;
        const uint32_t uAlo = st + TILE_H * 2;
        const uint32_t uBhi = st + 2 * TILE_H * 2;
        const uint32_t uBlo = st + 3 * TILE_H * 2;

#pragma unroll
        for (int ks = 0; ks < 2; ++ks) {
            const uint32_t ko = ks * 32;
            uint32_t ahi[4][4], alo[4][4], bhi[4][2], blo[4][2];
#pragma unroll
            for (int mi = 0; mi < 4; mi++) {
                LDSM4(ahi[mi], uAhi + a_loff + mi * (16 * SA * 2) + ko);
                LDSM4(alo[mi], uAlo + a_loff + mi * (16 * SA * 2) + ko);
            }
#pragma unroll
            for (int np = 0; np < 2; np++) {
                uint32_t tb[4];
                LDSM4(tb, uBhi + b_loff + np * (16 * SA * 2) + ko);
                bhi[2 * np][0] = tb[0]; bhi[2 * np][1] = tb[1];
                bhi[2 * np + 1][0] = tb[2]; bhi[2 * np + 1][1] = tb[3];
                LDSM4(tb, uBlo + b_loff + np * (16 * SA * 2) + ko);
                blo[2 * np][0] = tb[0]; blo[2 * np][1] = tb[1];
                blo[2 * np + 1][0] = tb[2]; blo[2 * np + 1][1] = tb[3];
            }
            // pass-outermost: same-acc MMAs are 16 issues apart
#pragma unroll
            for (int mi = 0; mi < 4; mi++)
#pragma unroll
                for (int ni = 0; ni < 4; ni++)
                    MMA16816(acc[mi][ni], ahi[mi], bhi[ni]);
#pragma unroll
            for (int mi = 0; mi < 4; mi++)
#pragma unroll
                for (int ni = 0; ni < 4; ni++)
                    MMA16816(acc[mi][ni], alo[mi], bhi[ni]);
#pragma unroll
            for (int mi = 0; mi < 4; mi++)
#pragma unroll
                for (int ni = 0; ni < 4; ni++)
                    MMA16816(acc[mi][ni], ahi[mi], blo[ni]);
        }
    }

#pragma unroll
    for (int mi = 0; mi < 4; mi++) {
        int row = bm + warp_m * 64 + mi * 16 + (lane >> 2);
#pragma unroll
        for (int ni = 0; ni < 4; ni++) {
            int col = bn + warp_n * 32 + ni * 8 + (lane & 3) * 2;
            float b0 = bias[col], b1 = bias[col + 1];
            float o0 = acc[mi][ni][0] + b0, o1 = acc[mi][ni][1] + b1;
            float o2 = acc[mi][ni][2] + b0, o3 = acc[mi][ni][3] + b1;
            if (SPLIT_OUT) {
                __nv_bfloat16 h0, h1, l0, l1;
                split2(o0, h0, l0); split2(o1, h1, l1);
                __nv_bfloat162 ph; ph.x = h0; ph.y = h1;
                __nv_bfloat162 pl; pl.x = l0; pl.y = l1;
                *(__nv_bfloat162*)(Chi + (size_t)row * N + col) = ph;
                *(__nv_bfloat162*)(Clo + (size_t)row * N + col) = pl;
                split2(o2, h0, l0); split2(o3, h1, l1);
                ph.x = h0; ph.y = h1; pl.x = l0; pl.y = l1;
                *(__nv_bfloat162*)(Chi + (size_t)(row + 8) * N + col) = ph;
                *(__nv_bfloat162*)(Clo + (size_t)(row + 8) * N + col) = pl;
            } else {
                *(float2*)(C + (size_t)row * N + col) = make_float2(o0, o1);
                *(float2*)(C + (size_t)(row + 8) * N + col) = make_float2(o2, o3);
            }
        }
    }
}

// ---------------------------------------------------------------------------
// Tensor-core flash attention. Same-acc MMAs interleaved across the two
// fragment chains (dep distance 1 -> 2, plus ldmatrix spacing).
// ---------------------------------------------------------------------------
#define QS 72
#define A_QH 0
#define A_QL (128 * QS)
#define A_KV0 (2 * 128 * QS)
#define KV_T (64 * QS)
#define KV_STAGE (4 * KV_T)
#define ATTN_SMEM ((A_KV0 + 2 * KV_STAGE) * 2)   // 110592 bytes

__global__ __launch_bounds__(256, 2) void attn_mma(
    const __nv_bfloat16* __restrict__ qkvh,
    const __nv_bfloat16* __restrict__ qkvl,
    __nv_bfloat16* __restrict__ chi, __nv_bfloat16* __restrict__ clo)
{
    extern __shared__ __nv_bfloat16 sh[];
    const uint32_t sbase = (uint32_t)__cvta_generic_to_shared(sh);
    const int tid = threadIdx.x;
    const int wid = tid >> 5, lane = tid & 31;
    const int q0 = blockIdx.x * 128;
    const int h  = blockIdx.y;
    const int t  = blockIdx.z;
    const size_t tbase = (size_t)t * B_DIM * D3 + h * HD_DIM;

    const int kr = tid >> 2, kc0 = (tid & 3) * 16;
    const uint32_t kvdst = (uint32_t)(kr * QS + kc0) * 2;

    {
        const int r = tid >> 1, c0 = (tid & 1) * 32;
        const __nv_bfloat16* qh_src = qkvh + tbase + (size_t)(q0 + r) * D3 + c0;
        const __nv_bfloat16* ql_src = qkvl + tbase + (size_t)(q0 + r) * D3 + c0;
        const uint32_t dh = sbase + (uint32_t)(A_QH + r * QS + c0) * 2;
        const uint32_t dl = sbase + (uint32_t)(A_QL + r * QS + c0) * 2;
#pragma unroll
        for (int j = 0; j < 4; j++) {
            cpa16(dh + j * 16, qh_src + j * 8);
            cpa16(dl + j * 16, ql_src + j * 8);
        }
        const size_t rowb = tbase + (size_t)kr * D3;
        const uint32_t s0 = sbase + A_KV0 * 2;
        cpa16(s0 + kvdst,                 qkvh + rowb + D_DIM + kc0);
        cpa16(s0 + kvdst + 16,            qkvh + rowb + D_DIM + kc0 + 8);
        cpa16(s0 + KV_T * 2 + kvdst,      qkvl + rowb + D_DIM + kc0);
        cpa16(s0 + KV_T * 2 + kvdst + 16, qkvl + rowb + D_DIM + kc0 + 8);
        cpa16(s0 + 2 * KV_T * 2 + kvdst,      qkvh + rowb + 2 * D_DIM + kc0);
        cpa16(s0 + 2 * KV_T * 2 + kvdst + 16, qkvh + rowb + 2 * D_DIM + kc0 + 8);
        cpa16(s0 + 3 * KV_T * 2 + kvdst,      qkvl + rowb + 2 * D_DIM + kc0);
        cpa16(s0 + 3 * KV_T * 2 + kvdst + 16, qkvl + rowb + 2 * D_DIM + kc0 + 8);
        cpa_commit();
    }

    const uint32_t q_loff =
        (uint32_t)(((wid * 16 + (lane & 15)) * QS + (lane >> 4) * 8) * 2);
    const uint32_t k_loff =
        (uint32_t)((((lane & 7) + ((lane >> 4) & 1) * 8) * QS +
                    ((lane >> 3) & 1) * 8) * 2);
    const uint32_t v_loff =
        (uint32_t)((((lane & 7) + ((lane >> 3) & 1) * 8) * QS +
                    ((lane >> 4) & 1) * 8) * 2);
    const uint32_t uQH = sbase + A_QH * 2, uQL = sbase + A_QL * 2;

    float m[2] = {-INFINITY, -INFINITY}, l[2] = {0.f, 0.f};
    float O[8][4];
#pragma unroll
    for (int dt = 0; dt < 8; dt++)
#pragma unroll
        for (int j = 0; j < 4; j++) O[dt][j] = 0.f;

    const int cA = (lane & 3) * 2;
    const int rA = lane >> 2;

    for (int kt = 0; kt < 8; ++kt) {
        cpa_wait0();
        __syncthreads();

        if (kt + 1 < 8) {
            const size_t rowb = tbase + (size_t)((kt + 1) * 64 + kr) * D3;
            const uint32_t s1 = sbase + (uint32_t)(A_KV0 + ((kt + 1) & 1) * KV_STAGE) * 2;
            cpa16(s1 + kvdst,                 qkvh + rowb + D_DIM + kc0);
            cpa16(s1 + kvdst + 16,            qkvh + rowb + D_DIM + kc0 + 8);
            cpa16(s1 + KV_T * 2 + kvdst,      qkvl + rowb + D_DIM + kc0);
            cpa16(s1 + KV_T * 2 + kvdst + 16, qkvl + rowb + D_DIM + kc0 + 8);
            cpa16(s1 + 2 * KV_T * 2 + kvdst,      qkvh + rowb + 2 * D_DIM + kc0);
            cpa16(s1 + 2 * KV_T * 2 + kvdst + 16, qkvh + rowb + 2 * D_DIM + kc0 + 8);
            cpa16(s1 + 3 * KV_T * 2 + kvdst,      qkvl + rowb + 2 * D_DIM + kc0);
            cpa16(s1 + 3 * KV_T * 2 + kvdst + 16, qkvl + rowb + 2 * D_DIM + kc0 + 8);
            cpa_commit();
        }

        const uint32_t stg = sbase + (uint32_t)(A_KV0 + (kt & 1) * KV_STAGE) * 2;
        const uint32_t uKH = stg;
        const uint32_t uKL = stg + KV_T * 2;
        const uint32_t uVH = stg + 2 * KV_T * 2;
        const uint32_t uVL = stg + 3 * KV_T * 2;

        float S[8][4];
#pragma unroll
        for (int nt = 0; nt < 8; nt++)
#pragma unroll
            for (int j = 0; j < 4; j++) S[nt][j] = 0.f;

#pragma unroll
        for (int kc = 0; kc < 4; ++kc) {
            const uint32_t ko = kc * 32;
            uint32_t qh[4], ql[4];
            LDSM4(qh, uQH + q_loff + ko);
            LDSM4(ql, uQL + q_loff + ko);
#pragma unroll
            for (int np = 0; np < 4; np++) {
                uint32_t th[4], tl[4];
                LDSM4(th, uKH + k_loff + np * (16 * QS * 2) + ko);
                LDSM4(tl, uKL + k_loff + np * (16 * QS * 2) + ko);
                uint32_t kh0[2] = {th[0], th[1]}, kh1[2] = {th[2], th[3]};
                uint32_t kl0[2] = {tl[0], tl[1]}, kl1[2] = {tl[2], tl[3]};
                // interleave the two acc chains: dep distance 2
                MMA16816(S[2 * np],     qh, kh0);
                MMA16816(S[2 * np + 1], qh, kh1);
                MMA16816(S[2 * np],     ql, kh0);
                MMA16816(S[2 * np + 1], ql, kh1);
                MMA16816(S[2 * np],     qh, kl0);
                MMA16816(S[2 * np + 1], qh, kl1);
            }
        }
#pragma unroll
        for (int nt = 0; nt < 8; nt++)
#pragma unroll
            for (int j = 0; j < 4; j++) S[nt][j] *= 0.125f;

        float sf[2];
#pragma unroll
        for (int rh = 0; rh < 2; rh++) {
            float mv = m[rh];
#pragma unroll
            for (int nt = 0; nt < 8; nt++)
                mv = fmaxf(mv, fmaxf(S[nt][2 * rh], S[nt][2 * rh + 1]));
            mv = fmaxf(mv, __shfl_xor_sync(0xffffffffu, mv, 1));
            mv = fmaxf(mv, __shfl_xor_sync(0xffffffffu, mv, 2));
            sf[rh] = __expf(m[rh] - mv);
            m[rh] = mv;
            float rs = 0.f;
#pragma unroll
            for (int nt = 0; nt < 8; nt++) {
                float p0 = __expf(S[nt][2 * rh] - mv);
                float p1 = __expf(S[nt][2 * rh + 1] - mv);
                S[nt][2 * rh] = p0; S[nt][2 * rh + 1] = p1;
                rs += p0 + p1;
            }
            rs += __shfl_xor_sync(0xffffffffu, rs, 1);
            rs += __shfl_xor_sync(0xffffffffu, rs, 2);
            l[rh] = l[rh] * sf[rh] + rs;
        }
#pragma unroll
        for (int dt = 0; dt < 8; dt++) {
            O[dt][0] *= sf[0]; O[dt][1] *= sf[0];
            O[dt][2] *= sf[1]; O[dt][3] *= sf[1];
        }

#pragma unroll
        for (int kc = 0; kc < 4; ++kc) {
            uint32_t ph[4], pl[4];
            {
                __nv_bfloat16 h0, h1, l0, l1;
                split2(S[2 * kc][0], h0, l0); split2(S[2 * kc][1], h1, l1);
                ph[0] = packbf(__bfloat162float(h0), __bfloat162float(h1));
                pl[0] = packbf(__bfloat162float(l0), __bfloat162float(l1));
                split2(S[2 * kc][2], h0, l0); split2(S[2 * kc][3], h1, l1);
                ph[1] = packbf(__bfloat162float(h0), __bfloat162float(h1));
                pl[1] = packbf(__bfloat162float(l0), __bfloat162float(l1));
                split2(S[2 * kc + 1][0], h0, l0); split2(S[2 * kc + 1][1], h1, l1);
                ph[2] = packbf(__bfloat162float(h0), __bfloat162float(h1));
                pl[2] = packbf(__bfloat162float(l0), __bfloat162float(l1));
                split2(S[2 * kc + 1][2], h0, l0); split2(S[2 * kc + 1][3], h1, l1);
                ph[3] = packbf(__bfloat162float(h0), __bfloat162float(h1));
                pl[3] = packbf(__bfloat162float(l0), __bfloat162float(l1));
            }
            const uint32_t kbase = kc * (16 * QS * 2);
#pragma unroll
            for (int dp = 0; dp < 4; dp++) {
                uint32_t th[4], tl[4];
                LDSM4T(th, uVH + v_loff + kbase + dp * 32);
                LDSM4T(tl, uVL + v_loff + kbase + dp * 32);
                uint32_t vh0[2] = {th[0], th[1]}, vh1[2] = {th[2], th[3]};
                uint32_t vl0[2] = {tl[0], tl[1]}, vl1[2] = {tl[2], tl[3]};
                MMA16816(O[2 * dp],     ph, vh0);
                MMA16816(O[2 * dp + 1], ph, vh1);
                MMA16816(O[2 * dp],     pl, vh0);
                MMA16816(O[2 * dp + 1], pl, vh1);
                MMA16816(O[2 * dp],     ph, vl0);
                MMA16816(O[2 * dp + 1], ph, vl1);
            }
        }
    }

    float inv0 = 1.f / l[0], inv1 = 1.f / l[1];
#pragma unroll
    for (int rh = 0; rh < 2; rh++) {
        const float inv = rh ? inv1 : inv0;
        const int row = q0 + wid * 16 + rA + rh * 8;
        const size_t rb = ((size_t)t * B_DIM + row) * D_DIM + h * HD_DIM;
#pragma unroll
        for (int dt = 0; dt < 8; dt++) {
            float o0 = O[dt][2 * rh] * inv, o1 = O[dt][2 * rh + 1] * inv;
            __nv_bfloat16 h0, h1, l0, l1;
            split2(o0, h0, l0); split2(o1, h1, l1);
            __nv_bfloat162 ph; ph.x = h0; ph.y = h1;
            __nv_bfloat162 pL; pL.x = l0; pL.y = l1;
            *(__nv_bfloat162*)(chi + rb + dt * 8 + cA) = ph;
            *(__nv_bfloat162*)(clo + rb + dt * 8 + cA) = pL;
        }
    }
}

// ---------------------------------------------------------------------------
// Stage 4
// ---------------------------------------------------------------------------
__global__ __launch_bounds__(256) void rownorm_kernel(
    const float* __restrict__ x, float* __restrict__ inv)
{
    int warp = threadIdx.x >> 5, lane = threadIdx.x & 31;
    int row = blockIdx.x * 8 + warp;
    const float* p = x + (size_t)row * D_DIM;
    float s = 0.f;
    for (int d = lane; d < D_DIM; d += 32) { float v = p[d]; s = fmaf(v, v, s); }
#pragma unroll
    for (int o = 16; o > 0; o >>= 1) s += __shfl_xor_sync(0xffffffffu, s, o);
    if (lane == 0) inv[row] = 1.f / fmaxf(sqrtf(s), 1e-8f);
}

__global__ __launch_bounds__(256) void mean_kernel(
    const float* __restrict__ x, const float* __restrict__ inv,
    float* __restrict__ mean)
{
    __shared__ float sinv[B_DIM];
    int t = blockIdx.x;
    int d = blockIdx.y * 256 + threadIdx.x;
    for (int i = threadIdx.x; i < B_DIM; i += 256) sinv[i] = inv[t * B_DIM + i];
    __syncthreads();
    const float* p = x + (size_t)t * B_DIM * D_DIM + d;
    float s = 0.f;
    for (int i = 0; i < B_DIM; i++) s = fmaf(p[(size_t)i * D_DIM], sinv[i], s);
    mean[t * D_DIM + d] = s * (1.f / B_DIM);
}

__global__ __launch_bounds__(256) void adj_kernel(
    const float* __restrict__ x, const float* __restrict__ inv,
    const float* __restrict__ mean, float* __restrict__ out)
{
    int warp = threadIdx.x >> 5, lane = threadIdx.x & 31;
    int row = blockIdx.x * 8 + warp;
    int t = row >> 9;
    const float* p = x + (size_t)row * D_DIM;
    const float* mp = mean + t * D_DIM;
    float s = 0.f;
    for (int d = lane; d < D_DIM; d += 32) s = fmaf(p[d], mp[d], s);
#pragma unroll
    for (int o = 16; o > 0; o >>= 1) s += __shfl_xor_sync(0xffffffffu, s, o);
    if (lane == 0) out[row] = s * inv[row];
}

// ---------------------------------------------------------------------------
extern "C" void kernel_launch(void* const* d_in, const int* in_sizes, int n_in,
                              void* d_out, int out_size)
{
    const float* node  = (const float*)d_in[0];
    const float* w_in  = (const float*)d_in[1];
    const float* b_in  = (const float*)d_in[2];
    const float* w_out = (const float*)d_in[3];
    const float* b_out = (const float*)d_in[4];
    float* out = (float*)d_out;

    float *o, *inv, *mean;
    __nv_bfloat16 *qkvh, *qkvl, *nhi, *nlo, *chi, *clo, *wihi, *wilo, *wohi, *wolo;
    cudaGetSymbolAddress((void**)&qkvh, g_qkvh);
    cudaGetSymbolAddress((void**)&qkvl, g_qkvl);
    cudaGetSymbolAddress((void**)&o,    g_out);
    cudaGetSymbolAddress((void**)&inv,  g_inv);
    cudaGetSymbolAddress((void**)&mean, g_mean);
    cudaGetSymbolAddress((void**)&nhi,  g_nhi);
    cudaGetSymbolAddress((void**)&nlo,  g_nlo);
    cudaGetSymbolAddress((void**)&chi,  g_chi);
    cudaGetSymbolAddress((void**)&clo,  g_clo);
    cudaGetSymbolAddress((void**)&wihi, g_wihi);
    cudaGetSymbolAddress((void**)&wilo, g_wilo);
    cudaGetSymbolAddress((void**)&wohi, g_wohi);
    cudaGetSymbolAddress((void**)&wolo, g_wolo);

    cudaFuncSetAttribute(gemm_mma<0>,
                         cudaFuncAttributeMaxDynamicSharedMemorySize, GEMM_SMEM);
    cudaFuncSetAttribute(gemm_mma<1>,
                         cudaFuncAttributeMaxDynamicSharedMemorySize, GEMM_SMEM);
    cudaFuncSetAttribute(attn_mma,
                         cudaFuncAttributeMaxDynamicSharedMemorySize, ATTN_SMEM);

    const int n_node = M_DIM * D_DIM;
    const int n_wi   = D3 * D_DIM;
    const int n_wo   = D_DIM * D_DIM;

    split_kernel<<<n_node / 1024, 256>>>(node, nhi, nlo, n_node);
    split_kernel<<<n_wi   / 1024, 256>>>(w_in, wihi, wilo, n_wi);
    split_kernel<<<n_wo   / 1024, 256>>>(w_out, wohi, wolo, n_wo);
    gemm_mma<1><<<dim3(D3 / 128, M_DIM / 128), 256, GEMM_SMEM>>>(
        nhi, nlo, wihi, wilo, b_in, nullptr, qkvh, qkvl, D3, D_DIM);
    attn_mma<<<dim3(B_DIM / 128, H_DIM, T_DIM), 256, ATTN_SMEM>>>(
        qkvh, qkvl, chi, clo);
    gemm_mma<0><<<dim3(D_DIM / 128, M_DIM / 128), 256, GEMM_SMEM>>>(
        chi, clo, wohi, wolo, b_out, o, nullptr, nullptr, D_DIM, D_DIM);
    rownorm_kernel<<<M_DIM / 8, 256>>>(o, inv);
    mean_kernel<<<dim3(T_DIM, D_DIM / 256), 256>>>(o, inv, mean);
    adj_kernel<<<M_DIM / 8, 256>>>(o, inv, mean, out);
}